// round 1
// baseline (speedup 1.0000x reference)
#include <cuda_runtime.h>
#include <math.h>

// SimpleNMS fused kernel for GB300 (sm_103a).
// scores: (16, 1024, 1024, 1) fp32 -> out same shape.
//
// Full pipeline (5 max-pools + elementwise) fused into ONE kernel using a
// 64x64 output tile with a 5-pixel halo (74x74 staged). All intermediates
// live in shared memory:
//   Ssc : staged scores (float, -inf padded outside image)
//   Am  : m0 mask, later reused for sm2 mask          (u8)
//   Bm  : sm1 mask                                    (u8)
//   Css : ss1 suppressed scores, later reused for ss2 (float)
//   Dm  : m1 mask                                     (u8)
//
// Stage regions shrink by 1 per pool (radius bookkeeping), so per-tile
// results are bit-exact vs. the global reference computation.

#define IMG_W   1024
#define IMG_H   1024
#define TILE    64
#define HALO    5
#define SWID    74            // TILE + 2*HALO
#define SP      76            // padded pitch (floats / bytes)
#define NT      256

__device__ __forceinline__ float fmax3(float a, float b, float c) {
    return fmaxf(a, fmaxf(b, c));
}

__global__ __launch_bounds__(NT)
void nms_kernel(const float* __restrict__ in, float* __restrict__ out)
{
    extern __shared__ unsigned char smraw[];
    float*         Ssc = reinterpret_cast<float*>(smraw);
    float*         Css = Ssc + SWID * SP;
    unsigned char* Am  = reinterpret_cast<unsigned char*>(Css + SWID * SP);
    unsigned char* Bm  = Am + SWID * SP;
    unsigned char* Dm  = Bm + SWID * SP;

    const int tid = threadIdx.x;
    const int bx = blockIdx.x, by = blockIdx.y, bz = blockIdx.z;
    const float* img  = in  + (size_t)bz * IMG_W * IMG_H;
    float*       oimg = out + (size_t)bz * IMG_W * IMG_H;

    const float NEG_INF = -__int_as_float(0x7f800000);

    // ---- Load scores with halo; -inf outside the image -------------------
    for (int i = tid; i < SWID * SWID; i += NT) {
        int r = i / SWID, c = i % SWID;
        int gy = by * TILE - HALO + r;
        int gx = bx * TILE - HALO + c;
        float v = NEG_INF;
        if ((unsigned)gy < (unsigned)IMG_H && (unsigned)gx < (unsigned)IMG_W)
            v = img[gy * IMG_W + gx];
        Ssc[r * SP + c] = v;
    }
    __syncthreads();

    // ---- Stage 1: m0 = (s == pool3(s)) over region [1,73) ----------------
    {
        const int a = 1, d = 72, R = 18;  // R = ceil(d/4)
        for (int i = tid; i < d * R; i += NT) {
            int r = a + i / R;
            int k = i % R;
            int c = a + min(4 * k, d - 4);
            const float* r0 = Ssc + (r - 1) * SP + (c - 1);
            const float* r1 = r0 + SP;
            const float* r2 = r1 + SP;
            float cm[6];
            #pragma unroll
            for (int j = 0; j < 6; j++) cm[j] = fmax3(r0[j], r1[j], r2[j]);
            #pragma unroll
            for (int j = 0; j < 4; j++) {
                float p = fmax3(cm[j], cm[j + 1], cm[j + 2]);
                Am[r * SP + c + j] = (r1[j + 1] == p) ? 1 : 0;
            }
        }
    }
    __syncthreads();

    // ---- Stage 2: sm1 = pool3(m0) > 0 ; ss1 = sm1 ? 0 : s  over [2,72) ---
    {
        const int a = 2, d = 70, R = 18;
        for (int i = tid; i < d * R; i += NT) {
            int r = a + i / R;
            int k = i % R;
            int c = a + min(4 * k, d - 4);
            const unsigned char* r0 = Am + (r - 1) * SP + (c - 1);
            const unsigned char* r1 = r0 + SP;
            const unsigned char* r2 = r1 + SP;
            unsigned char cm[6];
            #pragma unroll
            for (int j = 0; j < 6; j++) cm[j] = (unsigned char)(r0[j] | r1[j] | r2[j]);
            #pragma unroll
            for (int j = 0; j < 4; j++) {
                unsigned char s = (unsigned char)(cm[j] | cm[j + 1] | cm[j + 2]);
                int idx = r * SP + c + j;
                Bm[idx]  = s;
                Css[idx] = s ? 0.0f : Ssc[idx];
            }
        }
    }
    __syncthreads();

    // ---- Stage 3: nm1 = (ss1 == pool3(ss1)); m1 = m0 | (nm1 & ~sm1) [3,71)
    {
        const int a = 3, d = 68, R = 17;
        for (int i = tid; i < d * R; i += NT) {
            int r = a + i / R;
            int k = i % R;
            int c = a + min(4 * k, d - 4);
            const float* r0 = Css + (r - 1) * SP + (c - 1);
            const float* r1 = r0 + SP;
            const float* r2 = r1 + SP;
            float cm[6];
            #pragma unroll
            for (int j = 0; j < 6; j++) cm[j] = fmax3(r0[j], r1[j], r2[j]);
            #pragma unroll
            for (int j = 0; j < 4; j++) {
                float p = fmax3(cm[j], cm[j + 1], cm[j + 2]);
                int idx = r * SP + c + j;
                bool nm1 = (r1[j + 1] == p);
                bool m1  = Am[idx] || (nm1 && !Bm[idx]);
                Dm[idx] = m1 ? 1 : 0;
            }
        }
    }
    __syncthreads();

    // ---- Stage 4: sm2 = pool3(m1) > 0 ; ss2 = sm2 ? 0 : s  over [4,70) ---
    //      (writes Am (m0 dead) and Css (ss1 dead); reads only Dm, Ssc)
    {
        const int a = 4, d = 66, R = 17;
        for (int i = tid; i < d * R; i += NT) {
            int r = a + i / R;
            int k = i % R;
            int c = a + min(4 * k, d - 4);
            const unsigned char* r0 = Dm + (r - 1) * SP + (c - 1);
            const unsigned char* r1 = r0 + SP;
            const unsigned char* r2 = r1 + SP;
            unsigned char cm[6];
            #pragma unroll
            for (int j = 0; j < 6; j++) cm[j] = (unsigned char)(r0[j] | r1[j] | r2[j]);
            #pragma unroll
            for (int j = 0; j < 4; j++) {
                unsigned char s = (unsigned char)(cm[j] | cm[j + 1] | cm[j + 2]);
                int idx = r * SP + c + j;
                Am[idx]  = s;
                Css[idx] = s ? 0.0f : Ssc[idx];
            }
        }
    }
    __syncthreads();

    // ---- Stage 5: nm2; m2 = m1 | (nm2 & ~sm2); out = m2 ? s : 0  [5,69) --
    {
        const int a = 5, d = 64, R = 16;
        for (int i = tid; i < d * R; i += NT) {
            int r = a + i / R;
            int k = i % R;
            int c = a + 4 * k;               // d == 4*R, no clamp needed
            const float* r0 = Css + (r - 1) * SP + (c - 1);
            const float* r1 = r0 + SP;
            const float* r2 = r1 + SP;
            float cm[6];
            #pragma unroll
            for (int j = 0; j < 6; j++) cm[j] = fmax3(r0[j], r1[j], r2[j]);
            int gy = by * TILE + r - HALO;
            int gx = bx * TILE + c - HALO;
            float* orow = oimg + gy * IMG_W + gx;
            #pragma unroll
            for (int j = 0; j < 4; j++) {
                float p = fmax3(cm[j], cm[j + 1], cm[j + 2]);
                int idx = r * SP + c + j;
                bool nm2 = (r1[j + 1] == p);
                bool m2  = Dm[idx] || (nm2 && !Am[idx]);
                orow[j] = m2 ? Ssc[idx] : 0.0f;
            }
        }
    }
}

extern "C" void kernel_launch(void* const* d_in, const int* in_sizes, int n_in,
                              void* d_out, int out_size)
{
    const float* scores = (const float*)d_in[0];
    float* out = (float*)d_out;

    // 2 float buffers + 3 u8 buffers, each SWID*SP elements
    const size_t smem = (size_t)SWID * SP * (2 * sizeof(float) + 3);  // 61,864 B
    cudaFuncSetAttribute(nms_kernel,
                         cudaFuncAttributeMaxDynamicSharedMemorySize,
                         (int)smem);

    dim3 grid(IMG_W / TILE, IMG_H / TILE, 16);  // (16,16,16)
    nms_kernel<<<grid, NT, smem>>>(scores, out);
}

// round 5
// speedup vs baseline: 2.6089x; 2.6089x over previous
#include <cuda_runtime.h>

// SimpleNMS fused kernel, v2 — warp-row layout, register streaming, packed masks.
// scores: (16, 1024, 1024, 1) fp32 -> out, same shape.
//
// One CTA computes a 118x48 output tile from a 128x58 staged region (halo 5).
// Staged width 128 = 32 lanes x 4 cols; lane cg owns columns [4cg, 4cg+3].
// Horizontal pool neighbors come from __shfl; vertical pooling streams rows
// through a 3-deep register ring so each staged row is read once per stage.
// Masks are byte-packed 4-per-u32 ({0,1} bytes); horizontal OR = funnel shifts.
//
// smem: scores float[58][128] + three u32[58][32] mask planes = 51,968 B
//       -> 4 CTAs/SM.

#define IMG     1024
#define SROWS   58
#define SCOLS   128
#define SCOLW   32
#define HALO    5
#define TILE_X  118
#define TILE_Y  48
#define NT      256
#define NW      8
#define STRIP   8

struct SM {
    float    sc[SROWS][SCOLS];   // staged scores (-inf padded)
    unsigned M0[SROWS][SCOLW];   // m0 mask
    unsigned M1[SROWS][SCOLW];   // sm1, reused for sm2
    unsigned M2[SROWS][SCOLW];   // m1 mask
};

__device__ __forceinline__ float fmax3(float a, float b, float c) {
    return fmaxf(a, fmaxf(b, c));
}

// Per-lane validity mask for stage with region cols [a, 128-a): byte j of
// lane cg is 1 iff column 4cg+j is inside the region.
__device__ __forceinline__ unsigned vmask_for(int cg, int a) {
    unsigned vm = 0;
    int base = 4 * cg;
    #pragma unroll
    for (int j = 0; j < 4; j++)
        if (base + j >= a && base + j < SCOLS - a) vm |= 1u << (8 * j);
    return vm;
}

// Load one staged score row: lane's float4 + horizontal 3-max (needs one
// column from each neighbor lane via shuffle).
__device__ __forceinline__ void load_frow(const float (*buf)[SCOLS], int r, int cg,
                                          float4& hm, float4& v) {
    v = *reinterpret_cast<const float4*>(&buf[r][4 * cg]);
    float vl = __shfl_up_sync(0xffffffffu, v.w, 1);
    float vr = __shfl_down_sync(0xffffffffu, v.x, 1);
    hm.x = fmax3(vl, v.x, v.y);
    hm.y = fmax3(v.x, v.y, v.z);
    hm.z = fmax3(v.y, v.z, v.w);
    hm.w = fmax3(v.z, v.w, vr);
}

// Load one packed-mask row and return its horizontal 3-OR word.
__device__ __forceinline__ unsigned load_mrow(const unsigned (*buf)[SCOLW], int r, int cg) {
    unsigned wv = buf[r][cg];
    unsigned l  = __shfl_up_sync(0xffffffffu, wv, 1);
    unsigned rt = __shfl_down_sync(0xffffffffu, wv, 1);
    // bytes: (b-1 | b | b+1), pulling edge bytes from neighbor words
    return wv | __funnelshift_l(l, wv, 8) | __funnelshift_r(wv, rt, 8);
}

// Load one "suppressed scores" row: ss = maskbyte ? 0 : score.
// Returns horizontal 3-max of ss, the 4 center ss values, the 4 raw scores,
// and the center mask word.
__device__ __forceinline__ void load_srow(const float (*sc)[SCOLS],
                                          const unsigned (*sup)[SCOLW],
                                          int r, int cg,
                                          float4& hm, float4& ss, float4& v, unsigned& mw) {
    v = *reinterpret_cast<const float4*>(&sc[r][4 * cg]);
    unsigned m  = sup[r][cg];
    float vl = __shfl_up_sync(0xffffffffu, v.w, 1);
    float vr = __shfl_down_sync(0xffffffffu, v.x, 1);
    unsigned ml = __shfl_up_sync(0xffffffffu, m, 1);
    unsigned mr = __shfl_down_sync(0xffffffffu, m, 1);
    float sl = (ml & 0xff000000u) ? 0.f : vl;
    float s0 = (m  & 0x000000ffu) ? 0.f : v.x;
    float s1 = (m  & 0x0000ff00u) ? 0.f : v.y;
    float s2 = (m  & 0x00ff0000u) ? 0.f : v.z;
    float s3 = (m  & 0xff000000u) ? 0.f : v.w;
    float sr = (mr & 0x000000ffu) ? 0.f : vr;
    hm.x = fmax3(sl, s0, s1);
    hm.y = fmax3(s0, s1, s2);
    hm.z = fmax3(s1, s2, s3);
    hm.w = fmax3(s2, s3, sr);
    ss = make_float4(s0, s1, s2, s3);
    mw = m;
}

__device__ __forceinline__ unsigned eqmask(const float4& c, float p0, float p1,
                                           float p2, float p3) {
    return (c.x == p0 ? 0x00000001u : 0u) |
           (c.y == p1 ? 0x00000100u : 0u) |
           (c.z == p2 ? 0x00010000u : 0u) |
           (c.w == p3 ? 0x01000000u : 0u);
}

__global__ __launch_bounds__(NT, 4)
void nms_kernel(const float* __restrict__ in, float* __restrict__ out)
{
    extern __shared__ unsigned char raw[];
    SM* sm = reinterpret_cast<SM*>(raw);

    const int tid = threadIdx.x;
    const int w   = tid >> 5;
    const int cg  = tid & 31;
    const int bx = blockIdx.x, by = blockIdx.y, bz = blockIdx.z;
    const float* img  = in  + (size_t)bz * IMG * IMG;
    float*       oimg = out + (size_t)bz * IMG * IMG;
    const int gx0 = bx * TILE_X - HALO;
    const int gy0 = by * TILE_Y - HALO;
    const float NEG = -__int_as_float(0x7f800000);

    // ---- Stage 0: load staged scores (-inf outside image) ----------------
    #pragma unroll 1
    for (int r = w; r < SROWS; r += NW) {
        int gy = gy0 + r;
        bool yok = (unsigned)gy < IMG;
        const float* rp = img + (size_t)gy * IMG;
        int c0 = 4 * cg;
        int gx = gx0 + c0;
        float4 v;
        v.x = (yok && (unsigned)(gx + 0) < IMG) ? rp[gx + 0] : NEG;
        v.y = (yok && (unsigned)(gx + 1) < IMG) ? rp[gx + 1] : NEG;
        v.z = (yok && (unsigned)(gx + 2) < IMG) ? rp[gx + 2] : NEG;
        v.w = (yok && (unsigned)(gx + 3) < IMG) ? rp[gx + 3] : NEG;
        *reinterpret_cast<float4*>(&sm->sc[r][c0]) = v;
    }
    __syncthreads();

    // ---- Stage 1: m0 = (s == pool3(s)) -> M0, region a=1 -----------------
    {
        const int a = 1, E = SROWS - a;
        int r0 = max(w * STRIP, a), r1 = min(w * STRIP + STRIP, E);
        unsigned vm = vmask_for(cg, a);
        if (r0 < r1) {
            float4 hmA, hmB, hmC, vB, vC, t;
            load_frow(sm->sc, r0 - 1, cg, hmA, t);
            load_frow(sm->sc, r0,     cg, hmB, vB);
            #pragma unroll 1
            for (int r = r0; r < r1; r++) {
                load_frow(sm->sc, r + 1, cg, hmC, vC);
                float p0 = fmax3(hmA.x, hmB.x, hmC.x);
                float p1 = fmax3(hmA.y, hmB.y, hmC.y);
                float p2 = fmax3(hmA.z, hmB.z, hmC.z);
                float p3 = fmax3(hmA.w, hmB.w, hmC.w);
                sm->M0[r][cg] = eqmask(vB, p0, p1, p2, p3) & vm;
                hmA = hmB; hmB = hmC; vB = vC;
            }
        }
        __syncthreads();
    }

    // ---- Stage 2: sm1 = pool3(m0) -> M1, region a=2 ----------------------
    {
        const int a = 2, E = SROWS - a;
        int r0 = max(w * STRIP, a), r1 = min(w * STRIP + STRIP, E);
        unsigned vm = vmask_for(cg, a);
        if (r0 < r1) {
            unsigned hA = load_mrow(sm->M0, r0 - 1, cg);
            unsigned hB = load_mrow(sm->M0, r0,     cg);
            #pragma unroll 1
            for (int r = r0; r < r1; r++) {
                unsigned hC = load_mrow(sm->M0, r + 1, cg);
                sm->M1[r][cg] = (hA | hB | hC) & vm;
                hA = hB; hB = hC;
            }
        }
        __syncthreads();
    }

    // ---- Stage 3: nm1=(ss1==pool3(ss1)); m1 = m0 | (nm1 & ~sm1) -> M2 ----
    {
        const int a = 3, E = SROWS - a;
        int r0 = max(w * STRIP, a), r1 = min(w * STRIP + STRIP, E);
        unsigned vm = vmask_for(cg, a);
        if (r0 < r1) {
            float4 hmA, hmB, hmC, ssB, ssC, vB, vC, t4;
            unsigned mB, mC, tw;
            load_srow(sm->sc, sm->M1, r0 - 1, cg, hmA, t4, t4, tw);
            load_srow(sm->sc, sm->M1, r0,     cg, hmB, ssB, vB, mB);
            #pragma unroll 1
            for (int r = r0; r < r1; r++) {
                load_srow(sm->sc, sm->M1, r + 1, cg, hmC, ssC, vC, mC);
                float p0 = fmax3(hmA.x, hmB.x, hmC.x);
                float p1 = fmax3(hmA.y, hmB.y, hmC.y);
                float p2 = fmax3(hmA.z, hmB.z, hmC.z);
                float p3 = fmax3(hmA.w, hmB.w, hmC.w);
                unsigned nm = eqmask(ssB, p0, p1, p2, p3);
                sm->M2[r][cg] = (sm->M0[r][cg] | (nm & ~mB)) & vm;
                hmA = hmB; hmB = hmC; ssB = ssC; mB = mC;
            }
        }
        __syncthreads();
    }

    // ---- Stage 4: sm2 = pool3(m1) -> M1 (reuse), region a=4 --------------
    {
        const int a = 4, E = SROWS - a;
        int r0 = max(w * STRIP, a), r1 = min(w * STRIP + STRIP, E);
        unsigned vm = vmask_for(cg, a);
        if (r0 < r1) {
            unsigned hA = load_mrow(sm->M2, r0 - 1, cg);
            unsigned hB = load_mrow(sm->M2, r0,     cg);
            #pragma unroll 1
            for (int r = r0; r < r1; r++) {
                unsigned hC = load_mrow(sm->M2, r + 1, cg);
                sm->M1[r][cg] = (hA | hB | hC) & vm;
                hA = hB; hB = hC;
            }
        }
        __syncthreads();
    }

    // ---- Stage 5: nm2; m2 = m1 | (nm2 & ~sm2); out = m2 ? s : 0 ----------
    {
        const int a = 5, E = SROWS - a;
        int r0 = max(w * STRIP, a), r1 = min(w * STRIP + STRIP, E);
        if (r0 < r1) {
            float4 hmA, hmB, hmC, ssB, ssC, vB, vC, t4;
            unsigned mB, mC, tw;
            load_srow(sm->sc, sm->M1, r0 - 1, cg, hmA, t4, t4, tw);
            load_srow(sm->sc, sm->M1, r0,     cg, hmB, ssB, vB, mB);
            const int c0 = 4 * cg;
            const int gxb = gx0 + c0;
            #pragma unroll 1
            for (int r = r0; r < r1; r++) {
                load_srow(sm->sc, sm->M1, r + 1, cg, hmC, ssC, vC, mC);
                float p0 = fmax3(hmA.x, hmB.x, hmC.x);
                float p1 = fmax3(hmA.y, hmB.y, hmC.y);
                float p2 = fmax3(hmA.z, hmB.z, hmC.z);
                float p3 = fmax3(hmA.w, hmB.w, hmC.w);
                unsigned nm = eqmask(ssB, p0, p1, p2, p3);
                unsigned m2 = sm->M2[r][cg] | (nm & ~mB);
                int gy = gy0 + r;
                if ((unsigned)gy < IMG) {
                    float* orow = oimg + (size_t)gy * IMG;
                    if (c0 + 0 >= HALO && c0 + 0 < SCOLS - HALO && (unsigned)(gxb + 0) < IMG)
                        orow[gxb + 0] = (m2 & 0x000000ffu) ? vB.x : 0.f;
                    if (c0 + 1 >= HALO && c0 + 1 < SCOLS - HALO && (unsigned)(gxb + 1) < IMG)
                        orow[gxb + 1] = (m2 & 0x0000ff00u) ? vB.y : 0.f;
                    if (c0 + 2 >= HALO && c0 + 2 < SCOLS - HALO && (unsigned)(gxb + 2) < IMG)
                        orow[gxb + 2] = (m2 & 0x00ff0000u) ? vB.z : 0.f;
                    if (c0 + 3 >= HALO && c0 + 3 < SCOLS - HALO && (unsigned)(gxb + 3) < IMG)
                        orow[gxb + 3] = (m2 & 0xff000000u) ? vB.w : 0.f;
                }
                hmA = hmB; hmB = hmC; ssB = ssC; vB = vC; mB = mC;
            }
        }
    }
}

extern "C" void kernel_launch(void* const* d_in, const int* in_sizes, int n_in,
                              void* d_out, int out_size)
{
    const float* scores = (const float*)d_in[0];
    float* out = (float*)d_out;

    const size_t smem = sizeof(SM);   // 51,968 B
    cudaFuncSetAttribute(nms_kernel,
                         cudaFuncAttributeMaxDynamicSharedMemorySize,
                         (int)smem);

    dim3 grid((IMG + TILE_X - 1) / TILE_X,   // 9
              (IMG + TILE_Y - 1) / TILE_Y,   // 22
              16);
    nms_kernel<<<grid, NT, smem>>>(scores, out);
}

// round 6
// speedup vs baseline: 3.1510x; 1.2078x over previous
#include <cuda_runtime.h>

// SimpleNMS fused kernel, v2.5 — 0xFF byte masks + PRMT/LOP3 select paths,
// FSET-based equality packing, aligned float4 output stores, unrolled strips.
// scores: (16, 1024, 1024, 1) fp32 -> out, same shape.
//
// One CTA stages a 128x58 region; output tile 112x48 (cols [8,120) of the
// staged region -> 16B-aligned global stores). Masks are byte-packed
// 4-per-u32 with bytes 0xFF/0x00. Horizontal pool neighbors via __shfl;
// vertical pooling streams rows through a 3-deep register ring.
//
// smem: scores float[58][128] + three u32[58][32] mask planes = 51,968 B
//       -> 4 CTAs/SM.

#define IMG     1024
#define SROWS   58
#define SCOLS   128
#define SCOLW   32
#define TILE_X  112
#define TILE_Y  48
#define NT      256

struct SM {
    float    sc[SROWS][SCOLS];   // staged scores (-inf padded)
    unsigned M0[SROWS][SCOLW];   // m0 mask
    unsigned M1[SROWS][SCOLW];   // sm1, reused for sm2
    unsigned M2[SROWS][SCOLW];   // m1 mask
};

__device__ __forceinline__ float fmax3(float a, float b, float c) {
    return fmaxf(a, fmaxf(b, c));
}

// 0xFFFFFFFF / 0 full-width equality (FSET; fma-pipe, offloads ALU).
__device__ __forceinline__ unsigned fset_eq(float a, float b) {
    unsigned r;
    asm("set.eq.u32.f32 %0, %1, %2;" : "=r"(r) : "f"(a), "f"(b));
    return r;
}

// Pack 4 full-width eq results into one word with 0xFF/0x00 bytes (3 PRMT).
__device__ __forceinline__ unsigned pack_eq4(const float4& c, float p0, float p1,
                                             float p2, float p3) {
    unsigned e0 = fset_eq(c.x, p0);
    unsigned e1 = fset_eq(c.y, p1);
    unsigned e2 = fset_eq(c.z, p2);
    unsigned e3 = fset_eq(c.w, p3);
    unsigned t0 = __byte_perm(e0, e1, 0x0040);   // {e0.b0, e1.b0, -, -}
    unsigned t1 = __byte_perm(e2, e3, 0x0040);   // {e2.b0, e3.b0, -, -}
    return __byte_perm(t0, t1, 0x5410);          // {e0,e1,e2,e3} bytes
}

// Validity mask: byte j = 0xFF iff column 4cg+j in [a, 128-a).
__device__ __forceinline__ unsigned vmask_for(int cg, int a) {
    unsigned vm = 0;
    int base = 4 * cg;
    #pragma unroll
    for (int j = 0; j < 4; j++)
        if (base + j >= a && base + j < SCOLS - a) vm |= 0xFFu << (8 * j);
    return vm;
}

// Score row: float4 + horizontal 3-max (one column from each neighbor lane).
__device__ __forceinline__ void load_frow(const float (*buf)[SCOLS], int r, int cg,
                                          float4& hm, float4& v) {
    v = *reinterpret_cast<const float4*>(&buf[r][4 * cg]);
    float vl = __shfl_up_sync(0xffffffffu, v.w, 1);
    float vr = __shfl_down_sync(0xffffffffu, v.x, 1);
    hm.x = fmax3(vl, v.x, v.y);
    hm.y = fmax3(v.x, v.y, v.z);
    hm.z = fmax3(v.y, v.z, v.w);
    hm.w = fmax3(v.z, v.w, vr);
}

// Packed-mask row -> horizontal 3-OR word (bytes b-1|b|b+1).
__device__ __forceinline__ unsigned load_mrow(const unsigned (*buf)[SCOLW], int r, int cg) {
    unsigned wv = buf[r][cg];
    unsigned l  = __shfl_up_sync(0xffffffffu, wv, 1);
    unsigned rt = __shfl_down_sync(0xffffffffu, wv, 1);
    return wv | __funnelshift_l(l, wv, 8) | __funnelshift_r(wv, rt, 8);
}

// Suppressed-score row: ss_j = v_j & ~splat(mask byte j); shuffle the masked
// edge values (2 SHFL total). Returns horizontal 3-max of ss, the 4 center
// ss values, the 4 raw scores, and the center mask word.
__device__ __forceinline__ void load_srow(const float (*sc)[SCOLS],
                                          const unsigned (*sup)[SCOLW],
                                          int r, int cg,
                                          float4& hm, float4& ss, float4& v, unsigned& mw) {
    v = *reinterpret_cast<const float4*>(&sc[r][4 * cg]);
    unsigned m = sup[r][cg];
    float s0 = __uint_as_float(__float_as_uint(v.x) & ~__byte_perm(m, 0, 0x0000));
    float s1 = __uint_as_float(__float_as_uint(v.y) & ~__byte_perm(m, 0, 0x1111));
    float s2 = __uint_as_float(__float_as_uint(v.z) & ~__byte_perm(m, 0, 0x2222));
    float s3 = __uint_as_float(__float_as_uint(v.w) & ~__byte_perm(m, 0, 0x3333));
    float sl = __shfl_up_sync(0xffffffffu, s3, 1);
    float sr = __shfl_down_sync(0xffffffffu, s0, 1);
    hm.x = fmax3(sl, s0, s1);
    hm.y = fmax3(s0, s1, s2);
    hm.z = fmax3(s1, s2, s3);
    hm.w = fmax3(s2, s3, sr);
    ss = make_float4(s0, s1, s2, s3);
    mw = m;
}

__global__ __launch_bounds__(NT, 4)
void nms_kernel(const float* __restrict__ in, float* __restrict__ out)
{
    extern __shared__ unsigned char raw[];
    SM* sm = reinterpret_cast<SM*>(raw);

    const int tid = threadIdx.x;
    const int w   = tid >> 5;
    const int cg  = tid & 31;
    const int bx = blockIdx.x, by = blockIdx.y, bz = blockIdx.z;
    const float* img  = in  + (size_t)bz * IMG * IMG;
    float*       oimg = out + (size_t)bz * IMG * IMG;
    const int gx0 = bx * TILE_X - 8;     // staged col 0 (16B aligned)
    const int gy0 = by * TILE_Y - 5;     // staged row 0
    const float NEG = -__int_as_float(0x7f800000);

    // ---- Stage 0: load staged scores (-inf outside image) ----------------
    {
        const bool x_int = (bx >= 1) && (bx <= 8);
        const bool y_int = (by >= 1) && (by <= 20);
        const int c0 = 4 * cg;
        if (x_int && y_int) {
            #pragma unroll
            for (int k = 0; k < 8; k++) {
                int r = w + 8 * k;
                if (r >= SROWS) break;
                const float4 v = *reinterpret_cast<const float4*>(
                    img + (size_t)(gy0 + r) * IMG + gx0 + c0);
                *reinterpret_cast<float4*>(&sm->sc[r][c0]) = v;
            }
        } else {
            #pragma unroll
            for (int k = 0; k < 8; k++) {
                int r = w + 8 * k;
                if (r >= SROWS) break;
                int gy = gy0 + r;
                bool yok = (unsigned)gy < IMG;
                const float* rp = img + (size_t)gy * IMG;
                int gx = gx0 + c0;
                float4 v;
                v.x = (yok && (unsigned)(gx + 0) < IMG) ? rp[gx + 0] : NEG;
                v.y = (yok && (unsigned)(gx + 1) < IMG) ? rp[gx + 1] : NEG;
                v.z = (yok && (unsigned)(gx + 2) < IMG) ? rp[gx + 2] : NEG;
                v.w = (yok && (unsigned)(gx + 3) < IMG) ? rp[gx + 3] : NEG;
                *reinterpret_cast<float4*>(&sm->sc[r][c0]) = v;
            }
        }
    }
    __syncthreads();

    // ---- Stage 1: m0 = (s == pool3(s)) -> M0, rows [1,57), 7/warp --------
    {
        const int a = 1;
        const int r0 = a + 7 * w, r1 = min(r0 + 7, SROWS - a);
        const unsigned vm = vmask_for(cg, a);
        float4 hmA, hmB, hmC, vB, vC, t;
        load_frow(sm->sc, r0 - 1, cg, hmA, t);
        load_frow(sm->sc, r0,     cg, hmB, vB);
        #pragma unroll
        for (int k = 0; k < 7; k++) {
            int r = r0 + k;
            if (r >= r1) break;
            load_frow(sm->sc, r + 1, cg, hmC, vC);
            float p0 = fmax3(hmA.x, hmB.x, hmC.x);
            float p1 = fmax3(hmA.y, hmB.y, hmC.y);
            float p2 = fmax3(hmA.z, hmB.z, hmC.z);
            float p3 = fmax3(hmA.w, hmB.w, hmC.w);
            sm->M0[r][cg] = pack_eq4(vB, p0, p1, p2, p3) & vm;
            hmA = hmB; hmB = hmC; vB = vC;
        }
        __syncthreads();
    }

    // ---- Stage 2: sm1 = pool3(m0) -> M1, rows [2,56) ---------------------
    {
        const int a = 2;
        const int r0 = a + 7 * w, r1 = min(r0 + 7, SROWS - a);
        const unsigned vm = vmask_for(cg, a);
        unsigned hA = load_mrow(sm->M0, r0 - 1, cg);
        unsigned hB = load_mrow(sm->M0, r0,     cg);
        #pragma unroll
        for (int k = 0; k < 7; k++) {
            int r = r0 + k;
            if (r >= r1) break;
            unsigned hC = load_mrow(sm->M0, r + 1, cg);
            sm->M1[r][cg] = (hA | hB | hC) & vm;
            hA = hB; hB = hC;
        }
        __syncthreads();
    }

    // ---- Stage 3: nm1=(ss1==pool3(ss1)); m1 = m0 | (nm1 & ~sm1) -> M2 ----
    {
        const int a = 3;
        const int r0 = a + 7 * w, r1 = min(r0 + 7, SROWS - a);
        const unsigned vm = vmask_for(cg, a);
        float4 hmA, hmB, hmC, ssB, ssC, vB, vC, t4;
        unsigned mB, mC, tw;
        load_srow(sm->sc, sm->M1, r0 - 1, cg, hmA, t4, t4, tw);
        load_srow(sm->sc, sm->M1, r0,     cg, hmB, ssB, vB, mB);
        #pragma unroll
        for (int k = 0; k < 7; k++) {
            int r = r0 + k;
            if (r >= r1) break;
            load_srow(sm->sc, sm->M1, r + 1, cg, hmC, ssC, vC, mC);
            float p0 = fmax3(hmA.x, hmB.x, hmC.x);
            float p1 = fmax3(hmA.y, hmB.y, hmC.y);
            float p2 = fmax3(hmA.z, hmB.z, hmC.z);
            float p3 = fmax3(hmA.w, hmB.w, hmC.w);
            unsigned nm = pack_eq4(ssB, p0, p1, p2, p3);
            sm->M2[r][cg] = (sm->M0[r][cg] | (nm & ~mB)) & vm;
            hmA = hmB; hmB = hmC; ssB = ssC; mB = mC;
        }
        __syncthreads();
    }

    // ---- Stage 4: sm2 = pool3(m1) -> M1 (reuse), rows [4,54) -------------
    {
        const int a = 4;
        const int r0 = a + 7 * w, r1 = min(r0 + 7, SROWS - a);
        const unsigned vm = vmask_for(cg, a);
        unsigned hA = load_mrow(sm->M2, r0 - 1, cg);
        unsigned hB = load_mrow(sm->M2, r0,     cg);
        #pragma unroll
        for (int k = 0; k < 7; k++) {
            int r = r0 + k;
            if (r >= r1) break;
            unsigned hC = load_mrow(sm->M2, r + 1, cg);
            sm->M1[r][cg] = (hA | hB | hC) & vm;
            hA = hB; hB = hC;
        }
        __syncthreads();
    }

    // ---- Stage 5: nm2; m2 = m1 | (nm2 & ~sm2); out = s & expand(m2) ------
    //      rows [5,53), exactly 6/warp; aligned float4 stores, lanes 2..29.
    {
        const int r0 = 5 + 6 * w;
        float4 hmA, hmB, hmC, ssB, ssC, vB, vC, t4;
        unsigned mB, mC, tw;
        load_srow(sm->sc, sm->M1, r0 - 1, cg, hmA, t4, t4, tw);
        load_srow(sm->sc, sm->M1, r0,     cg, hmB, ssB, vB, mB);
        const int c0 = 4 * cg;
        const int gxo = gx0 + c0;
        const bool x_ok = (cg >= 2) && (cg < 30) && ((unsigned)gxo < IMG);
        #pragma unroll
        for (int k = 0; k < 6; k++) {
            int r = r0 + k;
            load_srow(sm->sc, sm->M1, r + 1, cg, hmC, ssC, vC, mC);
            float p0 = fmax3(hmA.x, hmB.x, hmC.x);
            float p1 = fmax3(hmA.y, hmB.y, hmC.y);
            float p2 = fmax3(hmA.z, hmB.z, hmC.z);
            float p3 = fmax3(hmA.w, hmB.w, hmC.w);
            unsigned nm = pack_eq4(ssB, p0, p1, p2, p3);
            unsigned m2 = sm->M2[r][cg] | (nm & ~mB);
            int gy = gy0 + r;
            if (x_ok && (unsigned)gy < IMG) {
                float4 o;
                o.x = __uint_as_float(__float_as_uint(vB.x) & __byte_perm(m2, 0, 0x0000));
                o.y = __uint_as_float(__float_as_uint(vB.y) & __byte_perm(m2, 0, 0x1111));
                o.z = __uint_as_float(__float_as_uint(vB.z) & __byte_perm(m2, 0, 0x2222));
                o.w = __uint_as_float(__float_as_uint(vB.w) & __byte_perm(m2, 0, 0x3333));
                *reinterpret_cast<float4*>(oimg + (size_t)gy * IMG + gxo) = o;
            }
            hmA = hmB; hmB = hmC; ssB = ssC; vB = vC; mB = mC;
        }
    }
}

extern "C" void kernel_launch(void* const* d_in, const int* in_sizes, int n_in,
                              void* d_out, int out_size)
{
    const float* scores = (const float*)d_in[0];
    float* out = (float*)d_out;

    const size_t smem = sizeof(SM);   // 51,968 B
    cudaFuncSetAttribute(nms_kernel,
                         cudaFuncAttributeMaxDynamicSharedMemorySize,
                         (int)smem);

    dim3 grid((IMG + TILE_X - 1) / TILE_X,   // 10
              (IMG + TILE_Y - 1) / TILE_Y,   // 22
              16);
    nms_kernel<<<grid, NT, smem>>>(scores, out);
}

// round 13
// speedup vs baseline: 3.7639x; 1.1945x over previous
#include <cuda_runtime.h>

// SimpleNMS fused kernel, v3 — merged mask stages (register-resident sm masks),
// no validity masks, fixed strips, 3 syncs, 2 smem mask planes.
// scores: (16, 1024, 1024, 1) fp32 -> out, same shape.
//
// One CTA stages 128x58; output tile 112x48 (staged cols [8,120), rows [5,53)).
// Edge garbage (shuffle clamp at cols 0/127, uninit mask rows 0/57) propagates
// at most 1 px per pool stage -> reaches only cols<=4/>=123, rows<=4/>=53,
// all outside the output window. So no column masks or row clamps are needed.
//
// Pipeline:  S1: m0 -> M0          (sync)
//            S23: sm1 in regs (halo-redundant), m1 -> M2   (sync)
//            S45: sm2 in regs, nm2, m2 -> global stores
//
// smem: float sc[58][128] + u32 M0[58][32] + u32 M2[58][32] = 44,544 B
//       -> 4 CTAs/SM.

#define IMG     1024
#define SROWS   58
#define SCOLS   128
#define SCOLW   32
#define TILE_X  112
#define TILE_Y  48
#define NT      256

struct SM {
    float    sc[SROWS][SCOLS];   // staged scores (-inf padded)
    unsigned M0[SROWS][SCOLW];   // m0 mask (0xFF/0x00 bytes, 4 px/u32)
    unsigned M2[SROWS][SCOLW];   // m1 mask
};

__device__ __forceinline__ float fmax3(float a, float b, float c) {
    return fmaxf(a, fmaxf(b, c));
}

// 0xFFFFFFFF / 0 full-width equality (FSET; fma-pipe, offloads ALU).
__device__ __forceinline__ unsigned fset_eq(float a, float b) {
    unsigned r;
    asm("set.eq.u32.f32 %0, %1, %2;" : "=r"(r) : "f"(a), "f"(b));
    return r;
}

// Pack 4 eq results into one word with 0xFF/0x00 bytes (3 PRMT).
__device__ __forceinline__ unsigned pack_eq4(const float4& c, float p0, float p1,
                                             float p2, float p3) {
    unsigned e0 = fset_eq(c.x, p0);
    unsigned e1 = fset_eq(c.y, p1);
    unsigned e2 = fset_eq(c.z, p2);
    unsigned e3 = fset_eq(c.w, p3);
    unsigned t0 = __byte_perm(e0, e1, 0x0040);
    unsigned t1 = __byte_perm(e2, e3, 0x0040);
    return __byte_perm(t0, t1, 0x5410);
}

// Score row: float4 + horizontal 3-max (neighbor columns via shuffle).
__device__ __forceinline__ void load_frow(const float (*buf)[SCOLS], int r, int cg,
                                          float4& hm, float4& v) {
    v = *reinterpret_cast<const float4*>(&buf[r][4 * cg]);
    float vl = __shfl_up_sync(0xffffffffu, v.w, 1);
    float vr = __shfl_down_sync(0xffffffffu, v.x, 1);
    hm.x = fmax3(vl, v.x, v.y);
    hm.y = fmax3(v.x, v.y, v.z);
    hm.z = fmax3(v.y, v.z, v.w);
    hm.w = fmax3(v.z, v.w, vr);
}

// Packed-mask row -> horizontal 3-OR word; also returns the center word.
__device__ __forceinline__ unsigned load_mrow2(const unsigned (*buf)[SCOLW], int r,
                                               unsigned cg, unsigned& center) {
    unsigned wv = buf[r][cg];
    center = wv;
    unsigned l  = __shfl_up_sync(0xffffffffu, wv, 1);
    unsigned rt = __shfl_down_sync(0xffffffffu, wv, 1);
    return wv | __funnelshift_l(l, wv, 8) | __funnelshift_r(wv, rt, 8);
}

// Suppressed-score row from a REGISTER mask word m:
// ss_j = v_j & ~splat(m byte j); horizontal 3-max via 2 shuffles.
__device__ __forceinline__ void load_ssrow(const float (*sc)[SCOLS], int r, int cg,
                                           unsigned m,
                                           float4& hm, float4& ss, float4& v) {
    v = *reinterpret_cast<const float4*>(&sc[r][4 * cg]);
    float s0 = __uint_as_float(__float_as_uint(v.x) & ~__byte_perm(m, 0, 0x0000));
    float s1 = __uint_as_float(__float_as_uint(v.y) & ~__byte_perm(m, 0, 0x1111));
    float s2 = __uint_as_float(__float_as_uint(v.z) & ~__byte_perm(m, 0, 0x2222));
    float s3 = __uint_as_float(__float_as_uint(v.w) & ~__byte_perm(m, 0, 0x3333));
    float sl = __shfl_up_sync(0xffffffffu, s3, 1);
    float sr = __shfl_down_sync(0xffffffffu, s0, 1);
    hm.x = fmax3(sl, s0, s1);
    hm.y = fmax3(s0, s1, s2);
    hm.z = fmax3(s1, s2, s3);
    hm.w = fmax3(s2, s3, sr);
    ss = make_float4(s0, s1, s2, s3);
}

__global__ __launch_bounds__(NT, 4)
void nms_kernel(const float* __restrict__ in, float* __restrict__ out)
{
    extern __shared__ unsigned char raw[];
    SM* sm = reinterpret_cast<SM*>(raw);

    const int tid = threadIdx.x;
    const int w   = tid >> 5;
    const int cg  = tid & 31;
    const int bx = blockIdx.x, by = blockIdx.y, bz = blockIdx.z;
    const float* img  = in  + (size_t)bz * IMG * IMG;
    float*       oimg = out + (size_t)bz * IMG * IMG;
    const int gx0 = bx * TILE_X - 8;     // staged col 0 (16B aligned)
    const int gy0 = by * TILE_Y - 5;     // staged row 0
    const float NEG = -__int_as_float(0x7f800000);

    // ---- Stage 0: load staged scores (-inf outside image) ----------------
    {
        const bool interior = (bx >= 1) && (bx <= 8) && (by >= 1) && (by <= 20);
        const int c0 = 4 * cg;
        if (interior) {
            #pragma unroll
            for (int k = 0; k < 8; k++) {
                int r = w + 8 * k;
                if (r >= SROWS) break;
                const float4 v = *reinterpret_cast<const float4*>(
                    img + (size_t)(gy0 + r) * IMG + gx0 + c0);
                *reinterpret_cast<float4*>(&sm->sc[r][c0]) = v;
            }
        } else {
            #pragma unroll
            for (int k = 0; k < 8; k++) {
                int r = w + 8 * k;
                if (r >= SROWS) break;
                int gy = gy0 + r;
                bool yok = (unsigned)gy < IMG;
                const float* rp = img + (size_t)gy * IMG;
                int gx = gx0 + c0;
                float4 v;
                v.x = (yok && (unsigned)(gx + 0) < IMG) ? rp[gx + 0] : NEG;
                v.y = (yok && (unsigned)(gx + 1) < IMG) ? rp[gx + 1] : NEG;
                v.z = (yok && (unsigned)(gx + 2) < IMG) ? rp[gx + 2] : NEG;
                v.w = (yok && (unsigned)(gx + 3) < IMG) ? rp[gx + 3] : NEG;
                *reinterpret_cast<float4*>(&sm->sc[r][c0]) = v;
            }
        }
    }
    __syncthreads();

    // ---- S1: m0 = (s == pool3(s)) -> M0, rows [1+7w, 8+7w), no masks -----
    {
        const int r0 = 1 + 7 * w;
        float4 hmA, hmB, hmC, vB, vC, t;
        load_frow(sm->sc, r0 - 1, cg, hmA, t);
        load_frow(sm->sc, r0,     cg, hmB, vB);
        #pragma unroll
        for (int k = 0; k < 7; k++) {
            int r = r0 + k;
            load_frow(sm->sc, r + 1, cg, hmC, vC);
            float p0 = fmax3(hmA.x, hmB.x, hmC.x);
            float p1 = fmax3(hmA.y, hmB.y, hmC.y);
            float p2 = fmax3(hmA.z, hmB.z, hmC.z);
            float p3 = fmax3(hmA.w, hmB.w, hmC.w);
            sm->M0[r][cg] = pack_eq4(vB, p0, p1, p2, p3);
            hmA = hmB; hmB = hmC; vB = vC;
        }
    }
    __syncthreads();

    // ---- S23: sm1 in regs; m1 = m0 | (nm1 & ~sm1) -> M2, rows [1+7w,8+7w)
    {
        const int r0 = 1 + 7 * w;
        unsigned c_t, cA, cB, cC;
        unsigned hq0 = load_mrow2(sm->M0, max(r0 - 2, 0), cg, c_t);
        unsigned hq1 = load_mrow2(sm->M0, r0 - 1, cg, c_t);
        unsigned hq2 = load_mrow2(sm->M0, r0,     cg, cA);
        unsigned sm1_prev = hq0 | hq1 | hq2;            // sm1 @ r0-1
        float4 hmA, hmB, hmC, ssB, ssC, sT, vT;
        load_ssrow(sm->sc, r0 - 1, cg, sm1_prev, hmA, sT, vT);
        unsigned hq3 = load_mrow2(sm->M0, r0 + 1, cg, cB);
        unsigned sm1_cur = hq1 | hq2 | hq3;             // sm1 @ r0
        load_ssrow(sm->sc, r0, cg, sm1_cur, hmB, ssB, vT);
        unsigned hq_r = hq2, hq_r1 = hq3;
        #pragma unroll
        for (int k = 0; k < 7; k++) {
            int r = r0 + k;
            unsigned hq_r2 = load_mrow2(sm->M0, min(r + 2, SROWS - 1), cg, cC);
            unsigned sm1_next = hq_r | hq_r1 | hq_r2;   // sm1 @ r+1
            load_ssrow(sm->sc, r + 1, cg, sm1_next, hmC, ssC, vT);
            float p0 = fmax3(hmA.x, hmB.x, hmC.x);
            float p1 = fmax3(hmA.y, hmB.y, hmC.y);
            float p2 = fmax3(hmA.z, hmB.z, hmC.z);
            float p3 = fmax3(hmA.w, hmB.w, hmC.w);
            unsigned nm = pack_eq4(ssB, p0, p1, p2, p3);
            sm->M2[r][cg] = cA | (nm & ~sm1_cur);       // m1 = m0 | (nm1 & ~sm1)
            hmA = hmB; hmB = hmC; ssB = ssC;
            sm1_cur = sm1_next; hq_r = hq_r1; hq_r1 = hq_r2;
            cA = cB; cB = cC;
        }
    }
    __syncthreads();

    // ---- S45: sm2 in regs; m2 = m1 | (nm2 & ~sm2); out, rows [5+6w,11+6w)
    {
        const int r0 = 5 + 6 * w;
        unsigned c_t, cA, cB, cC;
        unsigned hq0 = load_mrow2(sm->M2, r0 - 2, cg, c_t);
        unsigned hq1 = load_mrow2(sm->M2, r0 - 1, cg, c_t);
        unsigned hq2 = load_mrow2(sm->M2, r0,     cg, cA);
        unsigned sm2_prev = hq0 | hq1 | hq2;            // sm2 @ r0-1
        float4 hmA, hmB, hmC, ssB, ssC, sT, vT, vB, vC;
        load_ssrow(sm->sc, r0 - 1, cg, sm2_prev, hmA, sT, vT);
        unsigned hq3 = load_mrow2(sm->M2, r0 + 1, cg, cB);
        unsigned sm2_cur = hq1 | hq2 | hq3;             // sm2 @ r0
        load_ssrow(sm->sc, r0, cg, sm2_cur, hmB, ssB, vB);
        unsigned hq_r = hq2, hq_r1 = hq3;
        const int c0 = 4 * cg;
        const int gxo = gx0 + c0;
        const bool x_ok = (cg >= 2) && (cg < 30) && ((unsigned)gxo < IMG);
        #pragma unroll
        for (int k = 0; k < 6; k++) {
            int r = r0 + k;
            unsigned hq_r2 = load_mrow2(sm->M2, r + 2, cg, cC);
            unsigned sm2_next = hq_r | hq_r1 | hq_r2;   // sm2 @ r+1
            load_ssrow(sm->sc, r + 1, cg, sm2_next, hmC, ssC, vC);
            float p0 = fmax3(hmA.x, hmB.x, hmC.x);
            float p1 = fmax3(hmA.y, hmB.y, hmC.y);
            float p2 = fmax3(hmA.z, hmB.z, hmC.z);
            float p3 = fmax3(hmA.w, hmB.w, hmC.w);
            unsigned nm = pack_eq4(ssB, p0, p1, p2, p3);
            unsigned m2 = cA | (nm & ~sm2_cur);         // m2 = m1 | (nm2 & ~sm2)
            int gy = gy0 + r;
            if (x_ok && (unsigned)gy < IMG) {
                float4 o;
                o.x = __uint_as_float(__float_as_uint(vB.x) & __byte_perm(m2, 0, 0x0000));
                o.y = __uint_as_float(__float_as_uint(vB.y) & __byte_perm(m2, 0, 0x1111));
                o.z = __uint_as_float(__float_as_uint(vB.z) & __byte_perm(m2, 0, 0x2222));
                o.w = __uint_as_float(__float_as_uint(vB.w) & __byte_perm(m2, 0, 0x3333));
                *reinterpret_cast<float4*>(oimg + (size_t)gy * IMG + gxo) = o;
            }
            hmA = hmB; hmB = hmC; ssB = ssC; vB = vC;
            sm2_cur = sm2_next; hq_r = hq_r1; hq_r1 = hq_r2;
            cA = cB; cB = cC;
        }
    }
}

extern "C" void kernel_launch(void* const* d_in, const int* in_sizes, int n_in,
                              void* d_out, int out_size)
{
    const float* scores = (const float*)d_in[0];
    float* out = (float*)d_out;

    const size_t smem = sizeof(SM);   // 44,544 B
    cudaFuncSetAttribute(nms_kernel,
                         cudaFuncAttributeMaxDynamicSharedMemorySize,
                         (int)smem);

    dim3 grid((IMG + TILE_X - 1) / TILE_X,   // 10
              (IMG + TILE_Y - 1) / TILE_Y,   // 22
              16);
    nms_kernel<<<grid, NT, smem>>>(scores, out);
}